// round 6
// baseline (speedup 1.0000x reference)
#include <cuda_runtime.h>
#include <cuda_bf16.h>
#include <cstdint>

#define BATCH 4
#define SEQ   2048
#define EMB   1024
#define HDIM  1024
#define MROWS (BATCH*SEQ)

#define KCHUNK       16
#define ROW_HALVES   24                       // 16 data halves + 8 pad (48B pitch)
#define TILE_HALVES  (128*ROW_HALVES)
#define TILE_B       (TILE_HALVES*2)          // 6144 B
#define STAGE_HALVES (4*TILE_HALVES)          // Ah, Al, Bh, Bl
#define STAGE_B      (STAGE_HALVES*2)         // 24576 B
// static smem: 2*STAGE_B = 49152 B = 48 KB exactly

// ---------------- device scratch ----------------
__device__ __nv_bfloat16 g_Xhi[(size_t)MROWS*EMB];
__device__ __nv_bfloat16 g_Xlo[(size_t)MROWS*EMB];
__device__ __nv_bfloat16 g_Whi[(size_t)3*HDIM*EMB];
__device__ __nv_bfloat16 g_Wlo[(size_t)3*HDIM*EMB];
__device__ __nv_bfloat16 g_Qhi[(size_t)MROWS*HDIM];
__device__ __nv_bfloat16 g_Qlo[(size_t)MROWS*HDIM];
__device__ __nv_bfloat16 g_Khi[(size_t)MROWS*HDIM];
__device__ __nv_bfloat16 g_Klo[(size_t)MROWS*HDIM];
__device__ __nv_bfloat16 g_Vthi[(size_t)BATCH*HDIM*SEQ];  // [b][d][s]
__device__ __nv_bfloat16 g_Vtlo[(size_t)BATCH*HDIM*SEQ];
__device__ float         g_S  [(size_t)BATCH*SEQ*SEQ];
__device__ __nv_bfloat16 g_Phi[(size_t)BATCH*SEQ*SEQ];
__device__ __nv_bfloat16 g_Plo[(size_t)BATCH*SEQ*SEQ];

// ---------------- helpers ----------------
__device__ __forceinline__ uint32_t smem_u32(const void* p) {
    uint32_t a;
    asm("{ .reg .u64 t; cvta.to.shared.u64 t, %1; cvt.u32.u64 %0, t; }" : "=r"(a) : "l"(p));
    return a;
}
__device__ __forceinline__ void cp16(uint32_t saddr, const void* g) {
    asm volatile("cp.async.cg.shared.global [%0], [%1], 16;" :: "r"(saddr), "l"(g));
}
#define CP_COMMIT() asm volatile("cp.async.commit_group;" ::: "memory")
#define CP_WAIT1()  asm volatile("cp.async.wait_group 1;" ::: "memory")
#define CP_WAIT0()  asm volatile("cp.async.wait_group 0;" ::: "memory")

#define MMA(c, a, b) \
    asm volatile("mma.sync.aligned.m16n8k16.row.col.f32.bf16.bf16.f32 " \
        "{%0,%1,%2,%3}, {%4,%5,%6,%7}, {%8,%9}, {%0,%1,%2,%3};" \
        : "+f"((c)[0]), "+f"((c)[1]), "+f"((c)[2]), "+f"((c)[3]) \
        : "r"((a)[0]), "r"((a)[1]), "r"((a)[2]), "r"((a)[3]), "r"((b)[0]), "r"((b)[1]))

#define LDSM4(r0, r1, r2, r3, addr) \
    asm volatile("ldmatrix.sync.aligned.m8n8.x4.shared.b16 {%0,%1,%2,%3}, [%4];" \
        : "=r"(r0), "=r"(r1), "=r"(r2), "=r"(r3) : "r"(addr))

__device__ __forceinline__ void split2(float x, uint16_t& h, uint16_t& l) {
    __nv_bfloat16 hb = __float2bfloat16(x);
    __nv_bfloat16 lb = __float2bfloat16(x - __bfloat162float(hb));
    h = __bfloat16_as_ushort(hb);
    l = __bfloat16_as_ushort(lb);
}
__device__ __forceinline__ uint32_t pack2(uint16_t a, uint16_t b) {
    return (uint32_t)a | ((uint32_t)b << 16);
}

// ---------------- split kernels ----------------
__global__ __launch_bounds__(256) void split_x_kernel(const float* __restrict__ src) {
    size_t i = ((size_t)blockIdx.x * 256 + threadIdx.x) * 4;
    float4 v = *(const float4*)(src + i);
    uint16_t h[4], l[4];
    split2(v.x, h[0], l[0]); split2(v.y, h[1], l[1]);
    split2(v.z, h[2], l[2]); split2(v.w, h[3], l[3]);
    *(uint2*)((uint16_t*)g_Xhi + i) = make_uint2(pack2(h[0], h[1]), pack2(h[2], h[3]));
    *(uint2*)((uint16_t*)g_Xlo + i) = make_uint2(pack2(l[0], l[1]), pack2(l[2], l[3]));
}
__global__ __launch_bounds__(256) void split_w_kernel(
    const float* __restrict__ Wq, const float* __restrict__ Wk, const float* __restrict__ Wv)
{
    const int z = blockIdx.y;
    const float* src = (z == 0) ? Wq : (z == 1) ? Wk : Wv;
    size_t i = ((size_t)blockIdx.x * 256 + threadIdx.x) * 4;
    size_t off = (size_t)z * HDIM * EMB;
    float4 v = *(const float4*)(src + i);
    uint16_t h[4], l[4];
    split2(v.x, h[0], l[0]); split2(v.y, h[1], l[1]);
    split2(v.z, h[2], l[2]); split2(v.w, h[3], l[3]);
    *(uint2*)((uint16_t*)g_Whi + off + i) = make_uint2(pack2(h[0], h[1]), pack2(h[2], h[3]));
    *(uint2*)((uint16_t*)g_Wlo + off + i) = make_uint2(pack2(l[0], l[1]), pack2(l[2], l[3]));
}

// ---------------- stage load: 4 tiles of 128x16 bf16 via cp.async ----------------
__device__ __forceinline__ void load_stage(
    uint32_t sb, const __nv_bfloat16* __restrict__ Ah, const __nv_bfloat16* __restrict__ Al,
    const __nv_bfloat16* __restrict__ Bh, const __nv_bfloat16* __restrict__ Bl,
    int ldA, int ldB, int k0, int tid)
{
    const int row = tid >> 1, part = tid & 1;
    const uint32_t so = (uint32_t)(row * ROW_HALVES + part * 8) * 2;
    const size_t goA = (size_t)row * ldA + k0 + part * 8;
    const size_t goB = (size_t)row * ldB + k0 + part * 8;
    cp16(sb + 0 * TILE_B + so, Ah + goA);
    cp16(sb + 1 * TILE_B + so, Al + goA);
    cp16(sb + 2 * TILE_B + so, Bh + goB);
    cp16(sb + 3 * TILE_B + so, Bl + goB);
}

// ---------------- warp-MMA mainloop: acc += (Ah+Al)(Bh+Bl)^T (3-pass split) ----------------
// 128x128 CTA tile, 8 warps of 64x32, double-buffered cp.async, ldmatrix fragments.
__device__ __forceinline__ void gemm_mainloop(
    const __nv_bfloat16* __restrict__ Ah, const __nv_bfloat16* __restrict__ Al,
    const __nv_bfloat16* __restrict__ Bh, const __nv_bfloat16* __restrict__ Bl,
    int ldA, int ldB, int nChunks, float acc[4][4][4])
{
    __shared__ __align__(16) uint16_t sm[2 * STAGE_HALVES];

    const int tid  = threadIdx.x;
    const int lane = tid & 31, warp = tid >> 5;
    const int wr = warp >> 2, wc = warp & 3;
    const uint32_t sbase = smem_u32(sm);

    // ldmatrix per-lane byte offset within a tile: lanes 0-15 -> rows 0..15 (k 0-7),
    // lanes 16-31 -> rows 0..15 (k 8-15)
    const uint32_t lmo = (uint32_t)(((lane & 15) * ROW_HALVES) + ((lane >> 4) * 8)) * 2;
    const uint32_t a_tile_off = (uint32_t)(wr * 64 * ROW_HALVES) * 2 + lmo;              // + mt*16 rows
    const uint32_t b_tile_off = (uint32_t)(wc * 32 * ROW_HALVES) * 2 + lmo;              // + pair*16 rows

#pragma unroll
    for (int mt = 0; mt < 4; mt++)
#pragma unroll
        for (int nt = 0; nt < 4; nt++)
#pragma unroll
            for (int e = 0; e < 4; e++) acc[mt][nt][e] = 0.f;

    load_stage(sbase, Ah, Al, Bh, Bl, ldA, ldB, 0, tid);
    CP_COMMIT();

    for (int ic = 0; ic < nChunks; ic++) {
        const int buf = ic & 1;
        if (ic + 1 < nChunks) {
            load_stage(sbase + (buf ^ 1) * STAGE_B, Ah, Al, Bh, Bl, ldA, ldB, (ic + 1) * KCHUNK, tid);
            CP_COMMIT();
            CP_WAIT1();
        } else {
            CP_WAIT0();
        }
        __syncthreads();

        const uint32_t st = sbase + buf * STAGE_B;
        uint32_t a[4][4], bh[4][2], bl[4][2];
#pragma unroll
        for (int mt = 0; mt < 4; mt++)
            LDSM4(a[mt][0], a[mt][1], a[mt][2], a[mt][3],
                  st + a_tile_off + (uint32_t)(mt * 16 * ROW_HALVES) * 2);            // Ah
#pragma unroll
        for (int pr = 0; pr < 2; pr++) {
            uint32_t r0, r1, r2, r3;
            LDSM4(r0, r1, r2, r3,
                  st + 2 * TILE_B + b_tile_off + (uint32_t)(pr * 16 * ROW_HALVES) * 2);  // Bh
            bh[2*pr][0] = r0; bh[2*pr][1] = r2; bh[2*pr+1][0] = r1; bh[2*pr+1][1] = r3;
            LDSM4(r0, r1, r2, r3,
                  st + 3 * TILE_B + b_tile_off + (uint32_t)(pr * 16 * ROW_HALVES) * 2);  // Bl
            bl[2*pr][0] = r0; bl[2*pr][1] = r2; bl[2*pr+1][0] = r1; bl[2*pr+1][1] = r3;
        }
#pragma unroll
        for (int mt = 0; mt < 4; mt++)
#pragma unroll
            for (int nt = 0; nt < 4; nt++) MMA(acc[mt][nt], a[mt], bh[nt]);   // hi*hi
#pragma unroll
        for (int mt = 0; mt < 4; mt++)
#pragma unroll
            for (int nt = 0; nt < 4; nt++) MMA(acc[mt][nt], a[mt], bl[nt]);   // hi*lo
#pragma unroll
        for (int mt = 0; mt < 4; mt++)
            LDSM4(a[mt][0], a[mt][1], a[mt][2], a[mt][3],
                  st + TILE_B + a_tile_off + (uint32_t)(mt * 16 * ROW_HALVES) * 2);   // Al
#pragma unroll
        for (int mt = 0; mt < 4; mt++)
#pragma unroll
            for (int nt = 0; nt < 4; nt++) MMA(acc[mt][nt], a[mt], bh[nt]);   // lo*hi
        __syncthreads();
    }
}

// ---------------- kernel 1: QKV projection ----------------
__global__ __launch_bounds__(256, 2) void qkv_kernel(
    const float* __restrict__ bq, const float* __restrict__ bk, const float* __restrict__ bv)
{
    const int z = blockIdx.z;
    const int m0 = blockIdx.y * 128, n0 = blockIdx.x * 128;
    const __nv_bfloat16* Ah = g_Xhi + (size_t)m0 * EMB;
    const __nv_bfloat16* Al = g_Xlo + (size_t)m0 * EMB;
    const __nv_bfloat16* Bh = g_Whi + (size_t)z * HDIM * EMB + (size_t)n0 * EMB;
    const __nv_bfloat16* Bl = g_Wlo + (size_t)z * HDIM * EMB + (size_t)n0 * EMB;

    float acc[4][4][4];
    gemm_mainloop(Ah, Al, Bh, Bl, EMB, EMB, EMB / KCHUNK, acc);

    const float* bias = (z == 0) ? bq : (z == 1) ? bk : bv;
    const int tid = threadIdx.x;
    const int lane = tid & 31, warp = tid >> 5;
    const int wr = warp >> 2, wc = warp & 3;

    if (z < 2) {
        uint16_t* oh = (uint16_t*)(z ? g_Khi : g_Qhi);
        uint16_t* ol = (uint16_t*)(z ? g_Klo : g_Qlo);
#pragma unroll
        for (int mt = 0; mt < 4; mt++)
#pragma unroll
            for (int nt = 0; nt < 4; nt++) {
                int row0 = wr * 64 + mt * 16 + (lane >> 2);
                int col0 = wc * 32 + nt * 8 + (lane & 3) * 2;
                float b0 = __ldg(&bias[n0 + col0]);
                float b1 = __ldg(&bias[n0 + col0 + 1]);
#pragma unroll
                for (int h = 0; h < 2; h++) {
                    int row = row0 + 8 * h;
                    uint16_t h0, l0, h1, l1;
                    split2(acc[mt][nt][2 * h]     + b0, h0, l0);
                    split2(acc[mt][nt][2 * h + 1] + b1, h1, l1);
                    size_t o = (size_t)(m0 + row) * HDIM + n0 + col0;
                    *(uint32_t*)(oh + o) = pack2(h0, h1);
                    *(uint32_t*)(ol + o) = pack2(l0, l1);
                }
            }
    } else {
        const int b = m0 >> 11;
        const int s0 = m0 & (SEQ - 1);
        uint16_t* vh = (uint16_t*)g_Vthi + ((size_t)b * HDIM + n0) * SEQ + s0;
        uint16_t* vl = (uint16_t*)g_Vtlo + ((size_t)b * HDIM + n0) * SEQ + s0;
#pragma unroll
        for (int mt = 0; mt < 4; mt++)
#pragma unroll
            for (int nt = 0; nt < 4; nt++) {
                int row0 = wr * 64 + mt * 16 + (lane >> 2);
                int col0 = wc * 32 + nt * 8 + (lane & 3) * 2;
                float b0 = __ldg(&bias[n0 + col0]);
                float b1 = __ldg(&bias[n0 + col0 + 1]);
#pragma unroll
                for (int h = 0; h < 2; h++) {
                    int row = row0 + 8 * h;
                    uint16_t h0, l0, h1, l1;
                    split2(acc[mt][nt][2 * h]     + b0, h0, l0);
                    split2(acc[mt][nt][2 * h + 1] + b1, h1, l1);
                    vh[(size_t)col0 * SEQ + row]       = h0;
                    vl[(size_t)col0 * SEQ + row]       = l0;
                    vh[(size_t)(col0 + 1) * SEQ + row] = h1;
                    vl[(size_t)(col0 + 1) * SEQ + row] = l1;
                }
            }
    }
}

// ---------------- kernel 2: causal scores ----------------
__global__ __launch_bounds__(256, 2) void scores_kernel()
{
    if (blockIdx.x > blockIdx.y) return;
    const int b = blockIdx.z;
    const int m0 = blockIdx.y * 128, n0 = blockIdx.x * 128;
    const __nv_bfloat16* Ah = g_Qhi + ((size_t)(b * SEQ + m0)) * HDIM;
    const __nv_bfloat16* Al = g_Qlo + ((size_t)(b * SEQ + m0)) * HDIM;
    const __nv_bfloat16* Bh = g_Khi + ((size_t)(b * SEQ + n0)) * HDIM;
    const __nv_bfloat16* Bl = g_Klo + ((size_t)(b * SEQ + n0)) * HDIM;

    float acc[4][4][4];
    gemm_mainloop(Ah, Al, Bh, Bl, HDIM, HDIM, HDIM / KCHUNK, acc);

    const int tid = threadIdx.x;
    const int lane = tid & 31, warp = tid >> 5;
    const int wr = warp >> 2, wc = warp & 3;
    const float scale = 0.03125f;   // 1/sqrt(1024)
    float* S = g_S + (size_t)b * SEQ * SEQ;
#pragma unroll
    for (int mt = 0; mt < 4; mt++)
#pragma unroll
        for (int nt = 0; nt < 4; nt++) {
            int row0 = wr * 64 + mt * 16 + (lane >> 2);
            int col0 = wc * 32 + nt * 8 + (lane & 3) * 2;
#pragma unroll
            for (int h = 0; h < 2; h++) {
                int row = row0 + 8 * h;
                float2 v = { acc[mt][nt][2*h] * scale, acc[mt][nt][2*h+1] * scale };
                *(float2*)&S[(size_t)(m0 + row) * SEQ + n0 + col0] = v;
            }
        }
}

// ---------------- kernel 3: softmax -> split P (contiguous 8 elems/thread) ----------------
__global__ __launch_bounds__(256) void softmax_kernel()
{
    const int rowid = blockIdx.x;
    const int q = rowid & (SEQ - 1);
    const float* s = g_S + (size_t)rowid * SEQ;
    uint16_t* ph = (uint16_t*)g_Phi + (size_t)rowid * SEQ;
    uint16_t* pl = (uint16_t*)g_Plo + (size_t)rowid * SEQ;
    const int valid = q + 1;
    const int tid = threadIdx.x;
    const int i0 = tid * 8;
    __shared__ float red[256];

    float sv[8];
    *(float4*)&sv[0] = *(const float4*)(s + i0);
    *(float4*)&sv[4] = *(const float4*)(s + i0 + 4);

    float mx = -3.0e38f;
#pragma unroll
    for (int k = 0; k < 8; k++) if (i0 + k < valid) mx = fmaxf(mx, sv[k]);
    red[tid] = mx;
    __syncthreads();
    for (int st = 128; st > 0; st >>= 1) {
        if (tid < st) red[tid] = fmaxf(red[tid], red[tid + st]);
        __syncthreads();
    }
    mx = red[0];
    __syncthreads();

    float ev[8];
    float sum = 0.f;
#pragma unroll
    for (int k = 0; k < 8; k++) {
        float e = (i0 + k < valid) ? __expf(sv[k] - mx) : 0.f;
        ev[k] = e; sum += e;
    }
    red[tid] = sum;
    __syncthreads();
    for (int st = 128; st > 0; st >>= 1) {
        if (tid < st) red[tid] += red[tid + st];
        __syncthreads();
    }
    const float inv = 1.0f / red[0];

    uint16_t h[8], l[8];
#pragma unroll
    for (int k = 0; k < 8; k++) split2(ev[k] * inv, h[k], l[k]);   // masked ev==0 -> exact 0
    *(uint4*)(ph + i0) = make_uint4(pack2(h[0],h[1]), pack2(h[2],h[3]), pack2(h[4],h[5]), pack2(h[6],h[7]));
    *(uint4*)(pl + i0) = make_uint4(pack2(l[0],l[1]), pack2(l[2],l[3]), pack2(l[4],l[5]), pack2(l[6],l[7]));
}

// ---------------- kernel 4: O = P V (causal-bounded K loop) ----------------
__global__ __launch_bounds__(256, 2) void pv_kernel(float* __restrict__ O)
{
    const int b = blockIdx.z;
    const int m0 = blockIdx.y * 128, n0 = blockIdx.x * 128;
    const __nv_bfloat16* Ah = g_Phi  + (size_t)b * SEQ * SEQ + (size_t)m0 * SEQ;
    const __nv_bfloat16* Al = g_Plo  + (size_t)b * SEQ * SEQ + (size_t)m0 * SEQ;
    const __nv_bfloat16* Bh = g_Vthi + ((size_t)b * HDIM + n0) * SEQ;
    const __nv_bfloat16* Bl = g_Vtlo + ((size_t)b * HDIM + n0) * SEQ;
    const int nChunks = m0 / KCHUNK + 8;   // K in [0, m0+128)

    float acc[4][4][4];
    gemm_mainloop(Ah, Al, Bh, Bl, SEQ, SEQ, nChunks, acc);

    const int tid = threadIdx.x;
    const int lane = tid & 31, warp = tid >> 5;
    const int wr = warp >> 2, wc = warp & 3;
    float* C = O + (size_t)b * SEQ * HDIM;
#pragma unroll
    for (int mt = 0; mt < 4; mt++)
#pragma unroll
        for (int nt = 0; nt < 4; nt++) {
            int row0 = wr * 64 + mt * 16 + (lane >> 2);
            int col0 = wc * 32 + nt * 8 + (lane & 3) * 2;
#pragma unroll
            for (int h = 0; h < 2; h++) {
                int row = row0 + 8 * h;
                float2 v = { acc[mt][nt][2*h], acc[mt][nt][2*h+1] };
                *(float2*)&C[(size_t)(m0 + row) * HDIM + n0 + col0] = v;
            }
        }
}

// ---------------- launch: kernel launches ONLY ----------------
extern "C" void kernel_launch(void* const* d_in, const int* in_sizes, int n_in,
                              void* d_out, int out_size)
{
    (void)in_sizes; (void)n_in; (void)out_size;
    const float* X  = (const float*)d_in[0];
    const float* Wq = (const float*)d_in[1];
    const float* bq = (const float*)d_in[2];
    const float* Wk = (const float*)d_in[3];
    const float* bk = (const float*)d_in[4];
    const float* Wv = (const float*)d_in[5];
    const float* bv = (const float*)d_in[6];
    float* out = (float*)d_out;

    split_x_kernel<<<(MROWS * EMB) / 1024, 256>>>(X);
    split_w_kernel<<<dim3((HDIM * EMB) / 1024, 3), 256>>>(Wq, Wk, Wv);

    qkv_kernel<<<dim3(HDIM / 128, MROWS / 128, 3), 256>>>(bq, bk, bv);
    scores_kernel<<<dim3(SEQ / 128, SEQ / 128, BATCH), 256>>>();
    softmax_kernel<<<MROWS, 256>>>();
    pv_kernel<<<dim3(HDIM / 128, SEQ / 128, BATCH), 256>>>(out);
}